// round 11
// baseline (speedup 1.0000x reference)
#include <cuda_runtime.h>
#include <cuda_bf16.h>
#include <cstdint>

#define MAXN 100000
#define MAXE 1600000
#define E2CAP (MAXE + MAXN + 16)
#define FPS 67108864.0f            // 2^26 fixed-point scale for weighted degree
#define MAXNB 2048

// ---------------- device scratch (no allocations allowed) ----------------
__device__ unsigned long long g_pk[MAXN];     // packed: cnt<<46 | fixed-point weighted deg
__device__ float g_dinv[MAXN];
__device__ int   g_off[MAXN];
__device__ int   g_cur[MAXN];
__device__ int   g_bsums[MAXNB];
__device__ int   g_bsum_ex[MAXNB];
__device__ __align__(16) unsigned long long g_erec[E2CAP];  // src(17)|dst(17)|norm(30)
__device__ float2 g_p1[MAXN], g_p2[MAXN], g_p3[MAXN], g_p4[MAXN];
__device__ float  g_p5x[MAXN];
__device__ float  g_c[6 * 128];               // coef rows: c5, d4, d3, d2, d1, b5
__device__ unsigned g_bar_count = 0;
__device__ unsigned g_bar_sense = 0;          // monotonic across launches (equality-compared only)

// ---------------- grid-wide barrier (all blocks co-resident by construction) ----------------
__device__ __forceinline__ void grid_bar() {
    __syncthreads();
    if (threadIdx.x == 0) {
        __threadfence();
        unsigned s = *(volatile unsigned*)&g_bar_sense;
        unsigned a = atomicAdd(&g_bar_count, 1u);
        if (a == gridDim.x - 1) {
            *(volatile unsigned*)&g_bar_count = 0;
            __threadfence();
            atomicAdd(&g_bar_sense, 1u);
        } else {
            while (*(volatile unsigned*)&g_bar_sense == s) { __nanosleep(64); }
        }
    }
    __syncthreads();
}

// ---------------- 8-byte edge record ----------------
__device__ __forceinline__ unsigned long long pack_rec(int s, int d, float nv) {
    return (unsigned long long)(unsigned)s
         | ((unsigned long long)(unsigned)d << 17)
         | ((unsigned long long)(__float_as_uint(nv) >> 2) << 34);
}
__device__ __forceinline__ void dec_rec(unsigned long long r, int& s, int& d, float& nv) {
    s = (int)(r & 0x1FFFFULL);
    d = (int)((r >> 17) & 0x1FFFFULL);
    nv = __uint_as_float((unsigned)(r >> 34) << 2);
}

// ---------------- coefficient chain (block NB-1, phase 0) ----------------
__device__ __forceinline__ void mv_row(const float* in, const float* W,
                                       int IN, int OUT, float* out, int j) {
    if (j < OUT) {
        float s = 0.0f;
        for (int k = 0; k < IN; k++) s += in[k] * W[k * OUT + j];
        out[j] = s;
    }
}

__device__ void weights_chain(float* a, float* t,
                              const float* W1, const float* b1, const float* W2, const float* b2,
                              const float* W3, const float* b3, const float* W4, const float* b4,
                              const float* W5, const float* b5) {
    int j = threadIdx.x;
    if (j < 20) a[j] = W1[j];
    __syncthreads();
    mv_row(a, W2, 20, 40, t, j);  __syncthreads();
    mv_row(t, W3, 40, 60, a, j);  __syncthreads();
    mv_row(a, W4, 60, 80, t, j);  __syncthreads();
    mv_row(t, W5, 80, 100, &g_c[0 * 128], j); __syncthreads();

    if (j < 20) a[j] = b1[j];
    __syncthreads();
    mv_row(a, W2, 20, 40, t, j);  __syncthreads();
    mv_row(t, W3, 40, 60, a, j);  __syncthreads();
    mv_row(a, W4, 60, 80, t, j);  __syncthreads();
    mv_row(t, W5, 80, 100, &g_c[1 * 128], j); __syncthreads();

    if (j < 40) a[j] = b2[j];
    __syncthreads();
    mv_row(a, W3, 40, 60, t, j);  __syncthreads();
    mv_row(t, W4, 60, 80, a, j);  __syncthreads();
    mv_row(a, W5, 80, 100, &g_c[2 * 128], j); __syncthreads();

    if (j < 60) a[j] = b3[j];
    __syncthreads();
    mv_row(a, W4, 60, 80, t, j);  __syncthreads();
    mv_row(t, W5, 80, 100, &g_c[3 * 128], j); __syncthreads();

    if (j < 80) a[j] = b4[j];
    __syncthreads();
    mv_row(a, W5, 80, 100, &g_c[4 * 128], j); __syncthreads();

    if (j < 100) g_c[5 * 128 + j] = b5[j];
    __syncthreads();
}

// vector float2 atomic flush (sm_90+: single RED.64)
__device__ __forceinline__ void flush2(float2* addr, float ax, float ay) {
    atomicAdd(addr, make_float2(ax, ay));
}

// ---------------- edge-parallel float2 pass (8 edges/thread, run-merged) ----------------
__device__ void epass2(int e2p, int gtid, int NT, const float2* __restrict__ vin, float2* vout) {
    for (int t = gtid * 8; t < e2p; t += NT * 8) {
        ulonglong2 rA = *(const ulonglong2*)&g_erec[t];
        ulonglong2 rB = *(const ulonglong2*)&g_erec[t + 2];
        ulonglong2 rC = *(const ulonglong2*)&g_erec[t + 4];
        ulonglong2 rD = *(const ulonglong2*)&g_erec[t + 6];
        int ss[8], dd[8]; float cc[8];
        dec_rec(rA.x, ss[0], dd[0], cc[0]); dec_rec(rA.y, ss[1], dd[1], cc[1]);
        dec_rec(rB.x, ss[2], dd[2], cc[2]); dec_rec(rB.y, ss[3], dd[3], cc[3]);
        dec_rec(rC.x, ss[4], dd[4], cc[4]); dec_rec(rC.y, ss[5], dd[5], cc[5]);
        dec_rec(rD.x, ss[6], dd[6], cc[6]); dec_rec(rD.y, ss[7], dd[7], cc[7]);
        float vx[8], vy[8];
        #pragma unroll
        for (int q = 0; q < 8; q++) {
            float2 w = __ldg(&vin[ss[q]]);
            vx[q] = cc[q] * w.x;
            vy[q] = cc[q] * w.y;
        }
        float ax = vx[0], ay = vy[0];
        int cur = dd[0];
        #pragma unroll
        for (int q = 1; q < 8; q++) {
            if (dd[q] == cur) { ax += vx[q]; ay += vy[q]; }
            else { flush2(&vout[cur], ax, ay); cur = dd[q]; ax = vx[q]; ay = vy[q]; }
        }
        flush2(&vout[cur], ax, ay);
    }
}

// ---------------- THE kernel: every stage fused, grid barriers between ----------------
__global__ void __launch_bounds__(256, 4)
k_all(int n, int e, int e2p,
      const float* __restrict__ x, const int* __restrict__ ei, const float* __restrict__ ew,
      const float* __restrict__ W1, const float* __restrict__ b1,
      const float* __restrict__ W2, const float* __restrict__ b2,
      const float* __restrict__ W3, const float* __restrict__ b3,
      const float* __restrict__ W4, const float* __restrict__ b4,
      const float* __restrict__ W5, const float* __restrict__ b5,
      float* __restrict__ out) {
    __shared__ int   s_scan[256];
    __shared__ float s_a[128], s_t[128];
    __shared__ float s_c[6][100];
    __shared__ float s_v5[256], s_a1[256], s_a2[256], s_a3[256], s_a4[256];

    const int NB = gridDim.x;
    const int NT = NB * 256;
    const int tid = threadIdx.x;
    const int b = blockIdx.x;
    const int gtid = b * 256 + tid;
    const int e2 = e + n;
    const int C = (n + NB - 1) / NB;

    // ---- P0: zero pk/ALL states (p1 included: self term comes from the self-edge record),
    //          pad records, weights chain ----
    for (int i = gtid; i < n; i += NT) {
        g_pk[i] = 0ULL;
        float2 z = make_float2(0.f, 0.f);
        g_p1[i] = z; g_p2[i] = z; g_p3[i] = z; g_p4[i] = z;
        g_p5x[i] = 0.0f;
    }
    for (int i = e2 + gtid; i < e2p; i += NT) g_erec[i] = 0ULL;  // src0,dst0,norm0
    if (b == NB - 1)
        weights_chain(s_a, s_t, W1, b1, W2, b2, W3, b3, W4, b4, W5, b5);
    grid_bar();

    // ---- P1: weighted degree ----
    for (int q = gtid; q < e; q += NT) {
        int d = ei[e + q];
        unsigned long long v = (unsigned long long)(ew[q] * FPS + 0.5f) | (1ULL << 46);
        atomicAdd(&g_pk[d], v);
    }
    grid_bar();

    // ---- P2: per-chunk exclusive scan of counts ----
    {
        int c0 = b * C, c1 = min(n, c0 + C);
        int run = 0;
        for (int t0 = c0; t0 < c1; t0 += 256) {
            int i = t0 + tid;
            int v = (i < c1) ? (int)(g_pk[i] >> 46) : 0;
            s_scan[tid] = v;
            __syncthreads();
            for (int o = 1; o < 256; o <<= 1) {
                int tv = (tid >= o) ? s_scan[tid - o] : 0;
                __syncthreads();
                s_scan[tid] += tv;
                __syncthreads();
            }
            if (i < c1) g_off[i] = run + s_scan[tid] - v;
            run += s_scan[255];
            __syncthreads();
        }
        if (tid == 0) g_bsums[b] = run;
    }
    grid_bar();

    // ---- P3a: block 0 scans block sums ----
    if (b == 0) {
        int run = 0;
        for (int t0 = 0; t0 < NB; t0 += 256) {
            int idx = t0 + tid;
            int v = (idx < NB) ? g_bsums[idx] : 0;
            s_scan[tid] = v;
            __syncthreads();
            for (int o = 1; o < 256; o <<= 1) {
                int tv = (tid >= o) ? s_scan[tid - o] : 0;
                __syncthreads();
                s_scan[tid] += tv;
                __syncthreads();
            }
            if (idx < NB) g_bsum_ex[idx] = run + s_scan[tid] - v;
            run += s_scan[255];
            __syncthreads();
        }
    }
    grid_bar();

    // ---- P3b: finalize offsets, dinv, self edges (the ONLY self contribution) ----
    {
        int c0 = b * C, c1 = min(n, c0 + C);
        int pre = g_bsum_ex[b];
        for (int i = c0 + tid; i < c1; i += 256) {
            int o = g_off[i] + pre + i;         // +i: one self slot per prior node
            unsigned long long pk = g_pk[i];
            float deg = 1.0f + (float)(pk & ((1ULL << 46) - 1ULL)) * (1.0f / FPS);
            float di = rsqrtf(deg);
            float sn = di * di;
            g_dinv[i] = di;
            g_cur[i] = o + 1;
            g_erec[o] = pack_rec(i, i, sn);     // self edge at row head
        }
    }
    grid_bar();

    // ---- P4: scatter (dst-sorted, packed 8B records) ----
    for (int q = gtid; q < e; q += NT) {
        int s = ei[q], d = ei[e + q];
        float nv = g_dinv[s] * ew[q] * g_dinv[d];
        int pos = atomicAdd(&g_cur[d], 1);
        g_erec[pos] = pack_rec(s, d, nv);
    }
    grid_bar();

    // ---- P5: pass 1 (scalar x gather; self edge included in stream) ----
    for (int t = gtid * 8; t < e2p; t += NT * 8) {
        ulonglong2 rA = *(const ulonglong2*)&g_erec[t];
        ulonglong2 rB = *(const ulonglong2*)&g_erec[t + 2];
        ulonglong2 rC = *(const ulonglong2*)&g_erec[t + 4];
        ulonglong2 rD = *(const ulonglong2*)&g_erec[t + 6];
        int ss[8], dd[8]; float cc[8];
        dec_rec(rA.x, ss[0], dd[0], cc[0]); dec_rec(rA.y, ss[1], dd[1], cc[1]);
        dec_rec(rB.x, ss[2], dd[2], cc[2]); dec_rec(rB.y, ss[3], dd[3], cc[3]);
        dec_rec(rC.x, ss[4], dd[4], cc[4]); dec_rec(rC.y, ss[5], dd[5], cc[5]);
        dec_rec(rD.x, ss[6], dd[6], cc[6]); dec_rec(rD.y, ss[7], dd[7], cc[7]);
        float vx[8];
        #pragma unroll
        for (int q = 0; q < 8; q++) vx[q] = cc[q] * __ldg(&x[ss[q]]);
        float ax = vx[0], ay = cc[0];
        int cur = dd[0];
        #pragma unroll
        for (int q = 1; q < 8; q++) {
            if (dd[q] == cur) { ax += vx[q]; ay += cc[q]; }
            else { flush2(&g_p1[cur], ax, ay); cur = dd[q]; ax = vx[q]; ay = cc[q]; }
        }
        flush2(&g_p1[cur], ax, ay);
    }
    grid_bar();

    // ---- P6..P8: float2 passes ----
    epass2(e2p, gtid, NT, g_p1, g_p2);
    grid_bar();
    epass2(e2p, gtid, NT, g_p2, g_p3);
    grid_bar();
    epass2(e2p, gtid, NT, g_p3, g_p4);
    grid_bar();

    // ---- P9: pass 5, x-only ----
    for (int t = gtid * 8; t < e2p; t += NT * 8) {
        ulonglong2 rA = *(const ulonglong2*)&g_erec[t];
        ulonglong2 rB = *(const ulonglong2*)&g_erec[t + 2];
        ulonglong2 rC = *(const ulonglong2*)&g_erec[t + 4];
        ulonglong2 rD = *(const ulonglong2*)&g_erec[t + 6];
        int ss[8], dd[8]; float cc[8];
        dec_rec(rA.x, ss[0], dd[0], cc[0]); dec_rec(rA.y, ss[1], dd[1], cc[1]);
        dec_rec(rB.x, ss[2], dd[2], cc[2]); dec_rec(rB.y, ss[3], dd[3], cc[3]);
        dec_rec(rC.x, ss[4], dd[4], cc[4]); dec_rec(rC.y, ss[5], dd[5], cc[5]);
        dec_rec(rD.x, ss[6], dd[6], cc[6]); dec_rec(rD.y, ss[7], dd[7], cc[7]);
        float vx[8];
        #pragma unroll
        for (int q = 0; q < 8; q++) vx[q] = cc[q] * __ldg(&g_p4[ss[q]].x);
        float ax = vx[0];
        int cur = dd[0];
        #pragma unroll
        for (int q = 1; q < 8; q++) {
            if (dd[q] == cur) { ax += vx[q]; }
            else { atomicAdd(&g_p5x[cur], ax); cur = dd[q]; ax = vx[q]; }
        }
        atomicAdd(&g_p5x[cur], ax);
    }
    grid_bar();

    // ---- P10: final dense write-out ----
    for (int t = tid; t < 600; t += 256)
        s_c[t / 100][t % 100] = g_c[(t / 100) * 128 + (t % 100)];
    __syncthreads();
    for (int base = b * 256; base < n; base += NB * 256) {
        __syncthreads();
        int i = base + tid;
        if (i < n) {
            s_v5[tid] = g_p5x[i];
            s_a1[tid] = g_p1[i].y;
            s_a2[tid] = g_p2[i].y;
            s_a3[tid] = g_p3[i].y;
            s_a4[tid] = g_p4[i].y;
        }
        __syncthreads();
        for (int t = tid; t < 256 * 25; t += 256) {
            int wn = t / 25;
            int ch = t - wn * 25;
            int node = base + wn;
            if (node >= n) break;
            float v5 = s_v5[wn];
            float a1 = s_a1[wn], a2 = s_a2[wn], a3 = s_a3[wn], a4 = s_a4[wn];
            int j0 = ch * 4;
            float4 r;
            float* rr = &r.x;
            #pragma unroll
            for (int q = 0; q < 4; q++) {
                int j = j0 + q;
                rr[q] = fmaxf(v5 * s_c[0][j] + a4 * s_c[1][j] + a3 * s_c[2][j]
                            + a2 * s_c[3][j] + a1 * s_c[4][j] + s_c[5][j], 0.0f);
            }
            ((float4*)(out + (size_t)node * 100))[ch] = r;
        }
    }
}

// ---------------- launch: ONE kernel ----------------
extern "C" void kernel_launch(void* const* d_in, const int* in_sizes, int n_in,
                              void* d_out, int out_size) {
    const float* x  = (const float*)d_in[0];
    const int*   ei = (const int*)d_in[1];     // int32! (JAX demotes int64)
    const float* ew = (const float*)d_in[2];
    const float* W1 = (const float*)d_in[3];  const float* b1 = (const float*)d_in[4];
    const float* W2 = (const float*)d_in[5];  const float* b2 = (const float*)d_in[6];
    const float* W3 = (const float*)d_in[7];  const float* b3 = (const float*)d_in[8];
    const float* W4 = (const float*)d_in[9];  const float* b4 = (const float*)d_in[10];
    const float* W5 = (const float*)d_in[11]; const float* b5 = (const float*)d_in[12];
    float* out = (float*)d_out;

    int n = in_sizes[0];
    int e = in_sizes[2];
    int e2p = (e + n + 7) & ~7;

    // Grid sized so ALL blocks are co-resident (required by grid_bar).
    int dev = 0;
    cudaGetDevice(&dev);
    int sms = 148;
    cudaDeviceGetAttribute(&sms, cudaDevAttrMultiProcessorCount, dev);
    int maxb = 1;
    cudaOccupancyMaxActiveBlocksPerMultiprocessor(&maxb, k_all, 256, 0);
    if (maxb < 1) maxb = 1;
    if (maxb > 4) maxb = 4;
    int nb = sms * maxb;
    if (nb > MAXNB) nb = MAXNB;

    k_all<<<nb, 256>>>(n, e, e2p, x, ei, ew,
                       W1, b1, W2, b2, W3, b3, W4, b4, W5, b5, out);
    (void)n_in; (void)out_size;
}

// round 12
// speedup vs baseline: 1.2054x; 1.2054x over previous
#include <cuda_runtime.h>
#include <cuda_bf16.h>
#include <cstdint>

#define MAXN 100000
#define MAXE 1600000
#define E2CAP (MAXE + MAXN + 16)
#define FPS 67108864.0f            // 2^26 fixed-point scale for weighted degree

// ---------------- device scratch (no allocations allowed) ----------------
__device__ unsigned long long g_pk[MAXN];   // packed: cnt<<46 | fixed-point weighted deg
__device__ float g_dinv[MAXN];
__device__ int   g_off[MAXN + 1];
__device__ int   g_cur[MAXN];
__device__ int   g_bsums[128];
__device__ __align__(16) unsigned long long g_erec[E2CAP];  // src(17)|dst(17)|norm(30)
__device__ float2 g_p[5][MAXN];     // states 1..4: p[k] = (A^k x, A^k 1)
__device__ float  g_c[6 * 128];     // coef rows: c5, d4, d3, d2, d1, b5

// ---------------- 8-byte edge record ----------------
__device__ __forceinline__ unsigned long long pack_rec(int s, int d, float nv) {
    return (unsigned long long)(unsigned)s
         | ((unsigned long long)(unsigned)d << 17)
         | ((unsigned long long)(__float_as_uint(nv) >> 2) << 34);
}
__device__ __forceinline__ void dec_rec(unsigned long long r, int& s, int& d, float& nv) {
    s = (int)(r & 0x1FFFFULL);
    d = (int)((r >> 17) & 0x1FFFFULL);
    nv = __uint_as_float((unsigned)(r >> 34) << 2);
}
__device__ __forceinline__ void dec_rec_sn(unsigned long long r, int& s, float& nv) {
    s = (int)(r & 0x1FFFFULL);
    nv = __uint_as_float((unsigned)(r >> 34) << 2);
}

// vector float2 atomic flush (sm_90+: single RED.64)
__device__ __forceinline__ void flush2(float2* addr, float ax, float ay) {
    atomicAdd(addr, make_float2(ax, ay));
}

// ---------------- preprocessing ----------------
__global__ void k_init(int n) {
    int i = blockIdx.x * blockDim.x + threadIdx.x;
    if (i < n) g_pk[i] = 0ULL;
}

// edge_index is int32 on device (JAX x64-disabled demotes int64).
__global__ void k_edge_deg(int ecnt, const int* __restrict__ ei,
                           const float* __restrict__ ew) {
    int e = blockIdx.x * blockDim.x + threadIdx.x;
    if (e < ecnt) {
        int d = ei[ecnt + e];
        unsigned long long v = (unsigned long long)(ew[e] * FPS + 0.5f) | (1ULL << 46);
        atomicAdd(&g_pk[d], v);
    }
}

__global__ void k_scan1(int n) {
    __shared__ int sh[1024];
    int tid = threadIdx.x;
    int i = blockIdx.x * 1024 + tid;
    int v = (i < n) ? (int)(g_pk[i] >> 46) : 0;
    sh[tid] = v;
    __syncthreads();
    for (int off = 1; off < 1024; off <<= 1) {
        int t = (tid >= off) ? sh[tid - off] : 0;
        __syncthreads();
        sh[tid] += t;
        __syncthreads();
    }
    int incl = sh[tid];
    if (i < n) g_off[i] = incl - v;
    if (tid == 1023) g_bsums[blockIdx.x] = incl;
}

// Fused: bsums scan + final offsets (+i self slots) + dinv + self-edge emit + zero states + pads
__global__ void k_scan3f(int n, int nb, int e2) {
    __shared__ int sb[128];
    int tid = threadIdx.x;
    if (tid < 128) sb[tid] = (tid < nb) ? g_bsums[tid] : 0;
    __syncthreads();
    for (int off = 1; off < 128; off <<= 1) {
        int t = (tid >= off && tid < 128) ? sb[tid - off] : 0;
        __syncthreads();
        if (tid < 128) sb[tid] += t;
        __syncthreads();
    }
    if (blockIdx.x == 0) {
        if (tid == 0) g_off[n] = sb[nb - 1] + n;
        if (tid < 16) g_erec[e2 + tid] = 0ULL;   // pads: src0,dst0,norm0 -> no-op
    }
    int i = blockIdx.x * blockDim.x + tid;
    if (i < n) {
        int blk = i >> 10;
        int o = g_off[i] + (blk ? sb[blk - 1] : 0) + i;   // +i: one self slot per prior node
        unsigned long long pk = g_pk[i];
        float deg = 1.0f + (float)(pk & ((1ULL << 46) - 1ULL)) * (1.0f / FPS);
        float di = rsqrtf(deg);
        float sn = di * di;
        g_dinv[i] = di;
        g_off[i] = o;
        g_cur[i] = o + 1;                       // real edges start after self edge
        g_erec[o] = pack_rec(i, i, sn);         // self edge at row head
        float2 z = make_float2(0.f, 0.f);       // p1 starts at zero: self term is IN the stream
        g_p[1][i] = z; g_p[2][i] = z; g_p[3][i] = z; g_p[4][i] = z;
    }
}

__global__ void k_scatter(int ecnt, const int* __restrict__ ei,
                          const float* __restrict__ ew) {
    int e = blockIdx.x * blockDim.x + threadIdx.x;
    if (e < ecnt) {
        int s = ei[e];
        int d = ei[ecnt + e];
        int pos = atomicAdd(&g_cur[d], 1);
        float nv = g_dinv[s] * ew[e] * g_dinv[d];
        g_erec[pos] = pack_rec(s, d, nv);       // ONE 8B random store
    }
}

// ---------------- coefficient chain (device fn, run by block 0 of pass 1) ----------------
__device__ __forceinline__ void mv_row(const float* in, const float* W,
                                       int IN, int OUT, float* out, int j) {
    if (j < OUT) {
        float s = 0.0f;
        for (int k = 0; k < IN; k++) s += in[k] * W[k * OUT + j];
        out[j] = s;
    }
}

__device__ void weights_chain(const float* W1, const float* b1, const float* W2, const float* b2,
                              const float* W3, const float* b3, const float* W4, const float* b4,
                              const float* W5, const float* b5) {
    __shared__ float a[128], t[128];
    int j = threadIdx.x;

    if (j < 20) a[j] = W1[j];
    __syncthreads();
    mv_row(a, W2, 20, 40, t, j);  __syncthreads();
    mv_row(t, W3, 40, 60, a, j);  __syncthreads();
    mv_row(a, W4, 60, 80, t, j);  __syncthreads();
    mv_row(t, W5, 80, 100, &g_c[0 * 128], j); __syncthreads();

    if (j < 20) a[j] = b1[j];
    __syncthreads();
    mv_row(a, W2, 20, 40, t, j);  __syncthreads();
    mv_row(t, W3, 40, 60, a, j);  __syncthreads();
    mv_row(a, W4, 60, 80, t, j);  __syncthreads();
    mv_row(t, W5, 80, 100, &g_c[1 * 128], j); __syncthreads();

    if (j < 40) a[j] = b2[j];
    __syncthreads();
    mv_row(a, W3, 40, 60, t, j);  __syncthreads();
    mv_row(t, W4, 60, 80, a, j);  __syncthreads();
    mv_row(a, W5, 80, 100, &g_c[2 * 128], j); __syncthreads();

    if (j < 60) a[j] = b3[j];
    __syncthreads();
    mv_row(a, W4, 60, 80, t, j);  __syncthreads();
    mv_row(t, W5, 80, 100, &g_c[3 * 128], j); __syncthreads();

    if (j < 80) a[j] = b4[j];
    __syncthreads();
    mv_row(a, W5, 80, 100, &g_c[4 * 128], j); __syncthreads();

    if (j < 100) g_c[5 * 128 + j] = b5[j];
}

// ---------------- pass 1 (edge-parallel, 8 edges/thread, run-merged): p1 += {c*x[src], c} ----------------
__global__ void k_epass1(int e2, const float* __restrict__ x,
                         const float* __restrict__ W1, const float* __restrict__ b1,
                         const float* __restrict__ W2, const float* __restrict__ b2,
                         const float* __restrict__ W3, const float* __restrict__ b3,
                         const float* __restrict__ W4, const float* __restrict__ b4,
                         const float* __restrict__ W5, const float* __restrict__ b5) {
    if (blockIdx.x == 0)
        weights_chain(W1, b1, W2, b2, W3, b3, W4, b4, W5, b5);

    int t = (blockIdx.x * blockDim.x + threadIdx.x) * 8;
    if (t >= e2) return;
    ulonglong2 rA = *(const ulonglong2*)&g_erec[t];
    ulonglong2 rB = *(const ulonglong2*)&g_erec[t + 2];
    ulonglong2 rC = *(const ulonglong2*)&g_erec[t + 4];
    ulonglong2 rD = *(const ulonglong2*)&g_erec[t + 6];
    int ss[8], dd[8]; float cc[8];
    dec_rec(rA.x, ss[0], dd[0], cc[0]); dec_rec(rA.y, ss[1], dd[1], cc[1]);
    dec_rec(rB.x, ss[2], dd[2], cc[2]); dec_rec(rB.y, ss[3], dd[3], cc[3]);
    dec_rec(rC.x, ss[4], dd[4], cc[4]); dec_rec(rC.y, ss[5], dd[5], cc[5]);
    dec_rec(rD.x, ss[6], dd[6], cc[6]); dec_rec(rD.y, ss[7], dd[7], cc[7]);
    float vx[8];
    #pragma unroll
    for (int q = 0; q < 8; q++) vx[q] = cc[q] * __ldg(&x[ss[q]]);

    float2* out = g_p[1];
    float ax = vx[0], ay = cc[0];
    int cur = dd[0];
    #pragma unroll
    for (int q = 1; q < 8; q++) {
        if (dd[q] == cur) { ax += vx[q]; ay += cc[q]; }
        else { flush2(&out[cur], ax, ay); cur = dd[q]; ax = vx[q]; ay = cc[q]; }
    }
    flush2(&out[cur], ax, ay);
}

// ---------------- generic pass (edge-parallel, 8 edges/thread, run-merged) ----------------
__global__ void k_epass(int e2, int kin, int kout) {
    int t = (blockIdx.x * blockDim.x + threadIdx.x) * 8;
    if (t >= e2) return;
    const float2* __restrict__ vin = g_p[kin];
    ulonglong2 rA = *(const ulonglong2*)&g_erec[t];
    ulonglong2 rB = *(const ulonglong2*)&g_erec[t + 2];
    ulonglong2 rC = *(const ulonglong2*)&g_erec[t + 4];
    ulonglong2 rD = *(const ulonglong2*)&g_erec[t + 6];
    int ss[8], dd[8]; float cc[8];
    dec_rec(rA.x, ss[0], dd[0], cc[0]); dec_rec(rA.y, ss[1], dd[1], cc[1]);
    dec_rec(rB.x, ss[2], dd[2], cc[2]); dec_rec(rB.y, ss[3], dd[3], cc[3]);
    dec_rec(rC.x, ss[4], dd[4], cc[4]); dec_rec(rC.y, ss[5], dd[5], cc[5]);
    dec_rec(rD.x, ss[6], dd[6], cc[6]); dec_rec(rD.y, ss[7], dd[7], cc[7]);
    float vx[8], vy[8];
    #pragma unroll
    for (int q = 0; q < 8; q++) {
        float2 w = __ldg(&vin[ss[q]]);
        vx[q] = cc[q] * w.x;
        vy[q] = cc[q] * w.y;
    }
    float2* out = g_p[kout];
    float ax = vx[0], ay = vy[0];
    int cur = dd[0];
    #pragma unroll
    for (int q = 1; q < 8; q++) {
        if (dd[q] == cur) { ax += vx[q]; ay += vy[q]; }
        else { flush2(&out[cur], ax, ay); cur = dd[q]; ax = vx[q]; ay = vy[q]; }
    }
    flush2(&out[cur], ax, ay);
}

// ---------------- pass 5 (x-only, node-parallel pull; row includes self edge) + final write ----------------
__global__ void k_spmv5_final(int n, float* __restrict__ out) {
    __shared__ float sc[6][100];
    __shared__ float sv5[256], sa1[256], sa2[256], sa3[256], sa4[256];
    for (int t = threadIdx.x; t < 600; t += blockDim.x)
        sc[t / 100][t % 100] = g_c[(t / 100) * 128 + (t % 100)];

    int base = blockIdx.x * 256;
    int i = base + threadIdx.x;

    if (i < n) {
        const float2* __restrict__ vin = g_p[4];
        int e0 = g_off[i], e1 = g_off[i + 1];
        float ax = 0.0f;                         // self edge is in the row
        int e = e0;
        for (; e + 4 <= e1; e += 4) {
            unsigned long long r0 = __ldg(&g_erec[e]);
            unsigned long long r1 = __ldg(&g_erec[e + 1]);
            unsigned long long r2 = __ldg(&g_erec[e + 2]);
            unsigned long long r3 = __ldg(&g_erec[e + 3]);
            int s0, s1, s2, s3; float c0, c1, c2, c3;
            dec_rec_sn(r0, s0, c0); dec_rec_sn(r1, s1, c1);
            dec_rec_sn(r2, s2, c2); dec_rec_sn(r3, s3, c3);
            float v0 = __ldg(&vin[s0].x);
            float v1 = __ldg(&vin[s1].x);
            float v2 = __ldg(&vin[s2].x);
            float v3 = __ldg(&vin[s3].x);
            ax += c0 * v0 + c1 * v1 + c2 * v2 + c3 * v3;
        }
        for (; e < e1; e++) {
            int s; float c;
            dec_rec_sn(__ldg(&g_erec[e]), s, c);
            ax += c * __ldg(&vin[s].x);
        }
        sv5[threadIdx.x] = ax;
        sa1[threadIdx.x] = g_p[1][i].y;
        sa2[threadIdx.x] = g_p[2][i].y;
        sa3[threadIdx.x] = g_p[3][i].y;
        sa4[threadIdx.x] = g_p[4][i].y;
    }
    __syncthreads();

    for (int t = threadIdx.x; t < 256 * 25; t += blockDim.x) {
        int wnode = t / 25;
        int ch = t - wnode * 25;
        int node = base + wnode;
        if (node >= n) break;
        float v5 = sv5[wnode];
        float a1 = sa1[wnode], a2 = sa2[wnode], a3 = sa3[wnode], a4 = sa4[wnode];
        int j0 = ch * 4;
        float4 r;
        float* rr = &r.x;
        #pragma unroll
        for (int q = 0; q < 4; q++) {
            int j = j0 + q;
            rr[q] = fmaxf(v5 * sc[0][j] + a4 * sc[1][j] + a3 * sc[2][j]
                        + a2 * sc[3][j] + a1 * sc[4][j] + sc[5][j], 0.0f);
        }
        ((float4*)(out + (size_t)node * 100))[ch] = r;
    }
}

// ---------------- launch ----------------
extern "C" void kernel_launch(void* const* d_in, const int* in_sizes, int n_in,
                              void* d_out, int out_size) {
    const float* x  = (const float*)d_in[0];
    const int*   ei = (const int*)d_in[1];     // int32! (JAX demotes int64)
    const float* ew = (const float*)d_in[2];
    const float* W1 = (const float*)d_in[3];  const float* b1 = (const float*)d_in[4];
    const float* W2 = (const float*)d_in[5];  const float* b2 = (const float*)d_in[6];
    const float* W3 = (const float*)d_in[7];  const float* b3 = (const float*)d_in[8];
    const float* W4 = (const float*)d_in[9];  const float* b4 = (const float*)d_in[10];
    const float* W5 = (const float*)d_in[11]; const float* b5 = (const float*)d_in[12];
    float* out = (float*)d_out;

    int n = in_sizes[0];
    int e = in_sizes[2];
    int e2 = e + n;                    // edges + self loops

    int tb = 256;
    int gbN  = (n + tb - 1) / tb;
    int gbE  = (e + tb - 1) / tb;
    int nb   = (n + 1023) / 1024;
    int tE   = (e2 + 7) / 8;           // one thread per 8 edges
    int gbE2 = (tE + tb - 1) / tb;

    k_init<<<gbN, tb>>>(n);
    k_edge_deg<<<gbE, tb>>>(e, ei, ew);
    k_scan1<<<nb, 1024>>>(n);
    k_scan3f<<<gbN, tb>>>(n, nb, e2);
    k_scatter<<<gbE, tb>>>(e, ei, ew);

    k_epass1<<<gbE2, tb>>>(e2, x, W1, b1, W2, b2, W3, b3, W4, b4, W5, b5);
    k_epass<<<gbE2, tb>>>(e2, 1, 2);
    k_epass<<<gbE2, tb>>>(e2, 2, 3);
    k_epass<<<gbE2, tb>>>(e2, 3, 4);
    k_spmv5_final<<<gbN, tb>>>(n, out);

    (void)n_in; (void)out_size;
}

// round 13
// speedup vs baseline: 1.2074x; 1.0017x over previous
#include <cuda_runtime.h>
#include <cuda_bf16.h>
#include <cstdint>

#define MAXN 100000
#define MAXE 1600000
#define E2CAP (MAXE + MAXN + 16)
#define FPS 67108864.0f            // 2^26 fixed-point scale for weighted degree

// ---------------- device scratch (no allocations allowed) ----------------
// INVARIANT: g_pk is all-zero at kernel_launch entry (zero static init; k_scan3f
// re-zeroes each element after its single read, restoring the invariant per run).
__device__ unsigned long long g_pk[MAXN];   // packed: cnt<<46 | fixed-point weighted deg
__device__ float g_dinv[MAXN];
__device__ int   g_off[MAXN + 1];
__device__ int   g_cur[MAXN];
__device__ int   g_bsums[128];
__device__ __align__(16) unsigned long long g_erec[E2CAP];  // src(17)|dst(17)|norm(30)
__device__ float2 g_p[5][MAXN];     // states 1..4: p[k] = (A^k x, A^k 1)
__device__ float  g_c[6 * 128];     // coef rows: c5, d4, d3, d2, d1, b5

// ---------------- 8-byte edge record ----------------
__device__ __forceinline__ unsigned long long pack_rec(int s, int d, float nv) {
    return (unsigned long long)(unsigned)s
         | ((unsigned long long)(unsigned)d << 17)
         | ((unsigned long long)(__float_as_uint(nv) >> 2) << 34);
}
__device__ __forceinline__ void dec_rec(unsigned long long r, int& s, int& d, float& nv) {
    s = (int)(r & 0x1FFFFULL);
    d = (int)((r >> 17) & 0x1FFFFULL);
    nv = __uint_as_float((unsigned)(r >> 34) << 2);
}
__device__ __forceinline__ void dec_rec_sn(unsigned long long r, int& s, float& nv) {
    s = (int)(r & 0x1FFFFULL);
    nv = __uint_as_float((unsigned)(r >> 34) << 2);
}

// vector float2 atomic flush (sm_90+: single RED.64)
__device__ __forceinline__ void flush2(float2* addr, float ax, float ay) {
    atomicAdd(addr, make_float2(ax, ay));
}

// ---------------- preprocessing ----------------
// edge_index is int32 on device (JAX x64-disabled demotes int64).
__global__ void k_edge_deg(int ecnt, const int* __restrict__ ei,
                           const float* __restrict__ ew) {
    int e = blockIdx.x * blockDim.x + threadIdx.x;
    if (e < ecnt) {
        int d = ei[ecnt + e];
        unsigned long long v = (unsigned long long)(ew[e] * FPS + 0.5f) | (1ULL << 46);
        atomicAdd(&g_pk[d], v);
    }
}

// warp-shuffle block scan (1024 threads, 2 barriers)
__global__ void k_scan1(int n) {
    __shared__ int wsum[32];
    int tid = threadIdx.x;
    int i = blockIdx.x * 1024 + tid;
    int v = (i < n) ? (int)(g_pk[i] >> 46) : 0;
    int lane = tid & 31, w = tid >> 5;
    int s = v;
    #pragma unroll
    for (int o = 1; o < 32; o <<= 1) {
        int t = __shfl_up_sync(0xffffffffu, s, o);
        if (lane >= o) s += t;
    }
    if (lane == 31) wsum[w] = s;
    __syncthreads();
    if (w == 0) {
        int ws = wsum[lane];
        #pragma unroll
        for (int o = 1; o < 32; o <<= 1) {
            int t = __shfl_up_sync(0xffffffffu, ws, o);
            if (lane >= o) ws += t;
        }
        wsum[lane] = ws;
    }
    __syncthreads();
    int incl = s + (w ? wsum[w - 1] : 0);
    if (i < n) g_off[i] = incl - v;
    if (tid == 1023) g_bsums[blockIdx.x] = incl;
}

// Fused: bsums scan + final offsets (+i self slots) + dinv + self-edge emit
//        + zero states + pads + RESTORE g_pk=0 for the next replay
__global__ void k_scan3f(int n, int nb, int e2, int e2p) {
    __shared__ int sb[128];
    int tid = threadIdx.x;
    if (tid < 128) sb[tid] = (tid < nb) ? g_bsums[tid] : 0;
    __syncthreads();
    for (int off = 1; off < 128; off <<= 1) {
        int t = (tid >= off && tid < 128) ? sb[tid - off] : 0;
        __syncthreads();
        if (tid < 128) sb[tid] += t;
        __syncthreads();
    }
    if (blockIdx.x == 0) {
        if (tid == 0) g_off[n] = sb[nb - 1] + n;
        int p = e2 + tid;
        if (p < e2p) g_erec[p] = 0ULL;          // pads: src0,dst0,norm0 -> no-op
    }
    int i = blockIdx.x * blockDim.x + tid;
    if (i < n) {
        int blk = i >> 10;
        int o = g_off[i] + (blk ? sb[blk - 1] : 0) + i;   // +i: one self slot per prior node
        unsigned long long pk = g_pk[i];
        g_pk[i] = 0ULL;                          // restore invariant for next replay
        float deg = 1.0f + (float)(pk & ((1ULL << 46) - 1ULL)) * (1.0f / FPS);
        float di = rsqrtf(deg);
        float sn = di * di;
        g_dinv[i] = di;
        g_off[i] = o;
        g_cur[i] = o + 1;                       // real edges start after self edge
        g_erec[o] = pack_rec(i, i, sn);         // self edge at row head
        float2 z = make_float2(0.f, 0.f);       // p1 starts at zero: self term is IN the stream
        g_p[1][i] = z; g_p[2][i] = z; g_p[3][i] = z; g_p[4][i] = z;
    }
}

__global__ void k_scatter(int ecnt, const int* __restrict__ ei,
                          const float* __restrict__ ew) {
    int e = blockIdx.x * blockDim.x + threadIdx.x;
    if (e < ecnt) {
        int s = ei[e];
        int d = ei[ecnt + e];
        int pos = atomicAdd(&g_cur[d], 1);
        float nv = g_dinv[s] * ew[e] * g_dinv[d];
        g_erec[pos] = pack_rec(s, d, nv);       // ONE 8B random store
    }
}

// ---------------- coefficient chain (device fn, run by block 0 of pass 1) ----------------
__device__ __forceinline__ void mv_row(const float* in, const float* W,
                                       int IN, int OUT, float* out, int j) {
    if (j < OUT) {
        float s = 0.0f;
        for (int k = 0; k < IN; k++) s += in[k] * W[k * OUT + j];
        out[j] = s;
    }
}

__device__ void weights_chain(const float* W1, const float* b1, const float* W2, const float* b2,
                              const float* W3, const float* b3, const float* W4, const float* b4,
                              const float* W5, const float* b5) {
    __shared__ float a[128], t[128];
    int j = threadIdx.x;

    if (j < 20) a[j] = W1[j];
    __syncthreads();
    mv_row(a, W2, 20, 40, t, j);  __syncthreads();
    mv_row(t, W3, 40, 60, a, j);  __syncthreads();
    mv_row(a, W4, 60, 80, t, j);  __syncthreads();
    mv_row(t, W5, 80, 100, &g_c[0 * 128], j); __syncthreads();

    if (j < 20) a[j] = b1[j];
    __syncthreads();
    mv_row(a, W2, 20, 40, t, j);  __syncthreads();
    mv_row(t, W3, 40, 60, a, j);  __syncthreads();
    mv_row(a, W4, 60, 80, t, j);  __syncthreads();
    mv_row(t, W5, 80, 100, &g_c[1 * 128], j); __syncthreads();

    if (j < 40) a[j] = b2[j];
    __syncthreads();
    mv_row(a, W3, 40, 60, t, j);  __syncthreads();
    mv_row(t, W4, 60, 80, a, j);  __syncthreads();
    mv_row(a, W5, 80, 100, &g_c[2 * 128], j); __syncthreads();

    if (j < 60) a[j] = b3[j];
    __syncthreads();
    mv_row(a, W4, 60, 80, t, j);  __syncthreads();
    mv_row(t, W5, 80, 100, &g_c[3 * 128], j); __syncthreads();

    if (j < 80) a[j] = b4[j];
    __syncthreads();
    mv_row(a, W5, 80, 100, &g_c[4 * 128], j); __syncthreads();

    if (j < 100) g_c[5 * 128 + j] = b5[j];
}

// 8-edge chunk for pass 1 (x gather), carrying run accumulator across chunks
__device__ __forceinline__ void chunk1(int t, const float* __restrict__ x,
                                       float2* out, int& cur, float& ax, float& ay) {
    ulonglong2 rA = *(const ulonglong2*)&g_erec[t];
    ulonglong2 rB = *(const ulonglong2*)&g_erec[t + 2];
    ulonglong2 rC = *(const ulonglong2*)&g_erec[t + 4];
    ulonglong2 rD = *(const ulonglong2*)&g_erec[t + 6];
    int ss[8], dd[8]; float cc[8];
    dec_rec(rA.x, ss[0], dd[0], cc[0]); dec_rec(rA.y, ss[1], dd[1], cc[1]);
    dec_rec(rB.x, ss[2], dd[2], cc[2]); dec_rec(rB.y, ss[3], dd[3], cc[3]);
    dec_rec(rC.x, ss[4], dd[4], cc[4]); dec_rec(rC.y, ss[5], dd[5], cc[5]);
    dec_rec(rD.x, ss[6], dd[6], cc[6]); dec_rec(rD.y, ss[7], dd[7], cc[7]);
    float vx[8];
    #pragma unroll
    for (int q = 0; q < 8; q++) vx[q] = cc[q] * __ldg(&x[ss[q]]);
    #pragma unroll
    for (int q = 0; q < 8; q++) {
        if (dd[q] == cur) { ax += vx[q]; ay += cc[q]; }
        else {
            if (cur >= 0) flush2(&out[cur], ax, ay);
            cur = dd[q]; ax = vx[q]; ay = cc[q];
        }
    }
}

// ---------------- pass 1 (edge-parallel, 16 edges/thread, run-merged) ----------------
__global__ void k_epass1(int e2, const float* __restrict__ x,
                         const float* __restrict__ W1, const float* __restrict__ b1,
                         const float* __restrict__ W2, const float* __restrict__ b2,
                         const float* __restrict__ W3, const float* __restrict__ b3,
                         const float* __restrict__ W4, const float* __restrict__ b4,
                         const float* __restrict__ W5, const float* __restrict__ b5) {
    if (blockIdx.x == 0)
        weights_chain(W1, b1, W2, b2, W3, b3, W4, b4, W5, b5);

    int t = (blockIdx.x * blockDim.x + threadIdx.x) * 16;
    if (t >= e2) return;
    float2* out = g_p[1];
    int cur = -1; float ax = 0.f, ay = 0.f;
    chunk1(t, x, out, cur, ax, ay);
    chunk1(t + 8, x, out, cur, ax, ay);
    flush2(&out[cur], ax, ay);
}

// 8-edge chunk for generic float2 pass
__device__ __forceinline__ void chunk2(int t, const float2* __restrict__ vin,
                                       float2* out, int& cur, float& ax, float& ay) {
    ulonglong2 rA = *(const ulonglong2*)&g_erec[t];
    ulonglong2 rB = *(const ulonglong2*)&g_erec[t + 2];
    ulonglong2 rC = *(const ulonglong2*)&g_erec[t + 4];
    ulonglong2 rD = *(const ulonglong2*)&g_erec[t + 6];
    int ss[8], dd[8]; float cc[8];
    dec_rec(rA.x, ss[0], dd[0], cc[0]); dec_rec(rA.y, ss[1], dd[1], cc[1]);
    dec_rec(rB.x, ss[2], dd[2], cc[2]); dec_rec(rB.y, ss[3], dd[3], cc[3]);
    dec_rec(rC.x, ss[4], dd[4], cc[4]); dec_rec(rC.y, ss[5], dd[5], cc[5]);
    dec_rec(rD.x, ss[6], dd[6], cc[6]); dec_rec(rD.y, ss[7], dd[7], cc[7]);
    float vx[8], vy[8];
    #pragma unroll
    for (int q = 0; q < 8; q++) {
        float2 w = __ldg(&vin[ss[q]]);
        vx[q] = cc[q] * w.x;
        vy[q] = cc[q] * w.y;
    }
    #pragma unroll
    for (int q = 0; q < 8; q++) {
        if (dd[q] == cur) { ax += vx[q]; ay += vy[q]; }
        else {
            if (cur >= 0) flush2(&out[cur], ax, ay);
            cur = dd[q]; ax = vx[q]; ay = vy[q];
        }
    }
}

// ---------------- generic pass (edge-parallel, 16 edges/thread, run-merged) ----------------
__global__ void k_epass(int e2, int kin, int kout) {
    int t = (blockIdx.x * blockDim.x + threadIdx.x) * 16;
    if (t >= e2) return;
    const float2* __restrict__ vin = g_p[kin];
    float2* out = g_p[kout];
    int cur = -1; float ax = 0.f, ay = 0.f;
    chunk2(t, vin, out, cur, ax, ay);
    chunk2(t + 8, vin, out, cur, ax, ay);
    flush2(&out[cur], ax, ay);
}

// ---------------- pass 5 (x-only, node-parallel pull; row includes self edge) + final write ----------------
__global__ void k_spmv5_final(int n, float* __restrict__ out) {
    __shared__ float sc[6][100];
    __shared__ float sv5[256], sa1[256], sa2[256], sa3[256], sa4[256];
    for (int t = threadIdx.x; t < 600; t += blockDim.x)
        sc[t / 100][t % 100] = g_c[(t / 100) * 128 + (t % 100)];

    int base = blockIdx.x * 256;
    int i = base + threadIdx.x;

    if (i < n) {
        const float2* __restrict__ vin = g_p[4];
        int e0 = g_off[i], e1 = g_off[i + 1];
        float ax = 0.0f;                         // self edge is in the row
        int e = e0;
        for (; e + 4 <= e1; e += 4) {
            unsigned long long r0 = __ldg(&g_erec[e]);
            unsigned long long r1 = __ldg(&g_erec[e + 1]);
            unsigned long long r2 = __ldg(&g_erec[e + 2]);
            unsigned long long r3 = __ldg(&g_erec[e + 3]);
            int s0, s1, s2, s3; float c0, c1, c2, c3;
            dec_rec_sn(r0, s0, c0); dec_rec_sn(r1, s1, c1);
            dec_rec_sn(r2, s2, c2); dec_rec_sn(r3, s3, c3);
            float v0 = __ldg(&vin[s0].x);
            float v1 = __ldg(&vin[s1].x);
            float v2 = __ldg(&vin[s2].x);
            float v3 = __ldg(&vin[s3].x);
            ax += c0 * v0 + c1 * v1 + c2 * v2 + c3 * v3;
        }
        for (; e < e1; e++) {
            int s; float c;
            dec_rec_sn(__ldg(&g_erec[e]), s, c);
            ax += c * __ldg(&vin[s].x);
        }
        sv5[threadIdx.x] = ax;
        sa1[threadIdx.x] = g_p[1][i].y;
        sa2[threadIdx.x] = g_p[2][i].y;
        sa3[threadIdx.x] = g_p[3][i].y;
        sa4[threadIdx.x] = g_p[4][i].y;
    }
    __syncthreads();

    for (int t = threadIdx.x; t < 256 * 25; t += blockDim.x) {
        int wnode = t / 25;
        int ch = t - wnode * 25;
        int node = base + wnode;
        if (node >= n) break;
        float v5 = sv5[wnode];
        float a1 = sa1[wnode], a2 = sa2[wnode], a3 = sa3[wnode], a4 = sa4[wnode];
        int j0 = ch * 4;
        float4 r;
        float* rr = &r.x;
        #pragma unroll
        for (int q = 0; q < 4; q++) {
            int j = j0 + q;
            rr[q] = fmaxf(v5 * sc[0][j] + a4 * sc[1][j] + a3 * sc[2][j]
                        + a2 * sc[3][j] + a1 * sc[4][j] + sc[5][j], 0.0f);
        }
        ((float4*)(out + (size_t)node * 100))[ch] = r;
    }
}

// ---------------- launch ----------------
extern "C" void kernel_launch(void* const* d_in, const int* in_sizes, int n_in,
                              void* d_out, int out_size) {
    const float* x  = (const float*)d_in[0];
    const int*   ei = (const int*)d_in[1];     // int32! (JAX demotes int64)
    const float* ew = (const float*)d_in[2];
    const float* W1 = (const float*)d_in[3];  const float* b1 = (const float*)d_in[4];
    const float* W2 = (const float*)d_in[5];  const float* b2 = (const float*)d_in[6];
    const float* W3 = (const float*)d_in[7];  const float* b3 = (const float*)d_in[8];
    const float* W4 = (const float*)d_in[9];  const float* b4 = (const float*)d_in[10];
    const float* W5 = (const float*)d_in[11]; const float* b5 = (const float*)d_in[12];
    float* out = (float*)d_out;

    int n = in_sizes[0];
    int e = in_sizes[2];
    int e2 = e + n;                    // edges + self loops
    int e2p = (e2 + 15) & ~15;         // padded to 16

    int tb = 256;
    int gbN  = (n + tb - 1) / tb;
    int gbE  = (e + tb - 1) / tb;
    int nb   = (n + 1023) / 1024;
    int tE   = (e2 + 15) / 16;         // one thread per 16 edges
    int gbE2 = (tE + tb - 1) / tb;

    k_edge_deg<<<gbE, tb>>>(e, ei, ew);
    k_scan1<<<nb, 1024>>>(n);
    k_scan3f<<<gbN, tb>>>(n, nb, e2, e2p);
    k_scatter<<<gbE, tb>>>(e, ei, ew);

    k_epass1<<<gbE2, tb>>>(e2, x, W1, b1, W2, b2, W3, b3, W4, b4, W5, b5);
    k_epass<<<gbE2, tb>>>(e2, 1, 2);
    k_epass<<<gbE2, tb>>>(e2, 2, 3);
    k_epass<<<gbE2, tb>>>(e2, 3, 4);
    k_spmv5_final<<<gbN, tb>>>(n, out);

    (void)n_in; (void)out_size;
}